// round 16
// baseline (speedup 1.0000x reference)
#include <cuda_runtime.h>
#include <cuda_fp16.h>
#include <cstdint>

// Problem constants (fixed for MoELayer_20761871908984)
#define Bq     4
#define Sq     1024
#define Dq     1024
#define Hq     4096
#define Eq     8
#define Kq     2
#define NTOK   (Bq * Sq)        // 4096 tokens
#define MAXROW (NTOK * Kq)      // 8192 max (token, expert) rows
#define MAXTIL 72               // >= sum ceil(cnt_e/128) (bound 71)

// -------- device-global scratch (no runtime allocation allowed) --------
__device__ int    g_counts[Eq];
__device__ int    g_lists[Eq][NTOK];
__device__ int    g_odd_nonzero;             // sticky: 0 -> int64, 1 -> int32
__device__ int    g_done;                    // k_build completion counter
__device__ int    g_tile_e[MAXTIL];
__device__ int    g_tile_m[MAXTIL];
__device__ int    g_base[Eq];
__device__ int    g_ntiles;
__device__ __half g_xh [(size_t)NTOK * Dq];       //   8 MB x  (fp16 RNE)
__device__ __half g_hh [(size_t)MAXROW * Hq];     //  64 MB hidden (fp16 RNE)
__device__ __half g_w1h[(size_t)Eq * Dq * Hq];    //  64 MB W1 (fp16 RNE)
__device__ __half g_w2h[(size_t)Eq * Hq * Dq];    //  64 MB W2 (fp16 RNE)

// ---------------------------------------------------------------------
// k_prep: all independent front-end work in ONE launch.
// ---------------------------------------------------------------------
__global__ void k_prep(float* __restrict__ out, int n_out4,
                       const float* __restrict__ x,
                       const float* __restrict__ W1,
                       const int* __restrict__ a32) {
    const int i = blockIdx.x * blockDim.x + threadIdx.x;
    const int stride = gridDim.x * blockDim.x;

    if (i == 0) {
#pragma unroll
        for (int e = 0; e < Eq; e++) g_counts[e] = 0;
        g_done = 0;
    }

    // detect: odd 32-bit words nonzero <=> int32 layout
    if (i < NTOK * Kq / 2) {
        if (a32[2 * i + 1] != 0) atomicOr(&g_odd_nonzero, 1);
    }

    // zero output
    float4 z = make_float4(0.f, 0.f, 0.f, 0.f);
    for (int j = i; j < n_out4; j += stride)
        reinterpret_cast<float4*>(out)[j] = z;

    // x -> fp16 (8 elems/iter)
    const int nx8 = NTOK * Dq / 8;
    for (int j = i; j < nx8; j += stride) {
        float4 a = reinterpret_cast<const float4*>(x)[2 * j];
        float4 b = reinterpret_cast<const float4*>(x)[2 * j + 1];
        __half2 h0 = __floats2half2_rn(a.x, a.y);
        __half2 h1 = __floats2half2_rn(a.z, a.w);
        __half2 h2 = __floats2half2_rn(b.x, b.y);
        __half2 h3 = __floats2half2_rn(b.z, b.w);
        uint4 o;
        o.x = reinterpret_cast<unsigned&>(h0);
        o.y = reinterpret_cast<unsigned&>(h1);
        o.z = reinterpret_cast<unsigned&>(h2);
        o.w = reinterpret_cast<unsigned&>(h3);
        reinterpret_cast<uint4*>(g_xh)[j] = o;
    }

    // W1 -> fp16 (8 elems/iter)
    const int nw8 = Eq * Dq * Hq / 8;
    for (int j = i; j < nw8; j += stride) {
        float4 a = reinterpret_cast<const float4*>(W1)[2 * j];
        float4 b = reinterpret_cast<const float4*>(W1)[2 * j + 1];
        __half2 h0 = __floats2half2_rn(a.x, a.y);
        __half2 h1 = __floats2half2_rn(a.z, a.w);
        __half2 h2 = __floats2half2_rn(b.x, b.y);
        __half2 h3 = __floats2half2_rn(b.z, b.w);
        uint4 o;
        o.x = reinterpret_cast<unsigned&>(h0);
        o.y = reinterpret_cast<unsigned&>(h1);
        o.z = reinterpret_cast<unsigned&>(h2);
        o.w = reinterpret_cast<unsigned&>(h3);
        reinterpret_cast<uint4*>(g_w1h)[j] = o;
    }
}

// ---------------------------------------------------------------------
// k_build: per-expert token lists; LAST block also builds the tile table.
// ---------------------------------------------------------------------
__global__ void k_build(const int* __restrict__ a32) {
    int t = blockIdx.x * blockDim.x + threadIdx.x;
    if (t < NTOK) {
        int is64 = (g_odd_nonzero == 0);
        unsigned mask = 0;
#pragma unroll
        for (int j = 0; j < Kq; j++) {
            int e;
            if (is64) e = a32[(t * Kq + j) * 2];
            else      e = a32[t * Kq + j];
            mask |= 1u << (e & (Eq - 1));
        }
        while (mask) {
            int e = __ffs(mask) - 1;
            mask &= mask - 1;
            int p = atomicAdd(&g_counts[e], 1);
            g_lists[e][p] = t;
        }
    }
    __syncthreads();
    if (threadIdx.x == 0) {
        __threadfence();
        int done = atomicAdd(&g_done, 1);
        if (done == (int)gridDim.x - 1) {
            int base = 0, nt = 0;
#pragma unroll
            for (int e = 0; e < Eq; e++) {
                int cnt = g_counts[e];
                g_base[e] = base;
                for (int m0 = 0; m0 < cnt && nt < MAXTIL; m0 += 128) {
                    g_tile_e[nt] = e;
                    g_tile_m[nt] = m0;
                    nt++;
                }
                base += cnt;
            }
            g_ntiles = nt;
        }
    }
}

// ---------------------------------------------------------------------
// fp16 MMA + ldmatrix + cp.async helpers
// ---------------------------------------------------------------------
__device__ __forceinline__ void mma_f16(float& d0, float& d1, float& d2, float& d3,
                                        unsigned a0, unsigned a1, unsigned a2, unsigned a3,
                                        unsigned b0, unsigned b1) {
    asm volatile(
        "mma.sync.aligned.m16n8k16.row.col.f32.f16.f16.f32 "
        "{%0,%1,%2,%3},{%4,%5,%6,%7},{%8,%9},{%0,%1,%2,%3};\n"
        : "+f"(d0), "+f"(d1), "+f"(d2), "+f"(d3)
        : "r"(a0), "r"(a1), "r"(a2), "r"(a3), "r"(b0), "r"(b1));
}

__device__ __forceinline__ void ldsm_x4(unsigned& r0, unsigned& r1, unsigned& r2, unsigned& r3,
                                        uint32_t addr) {
    asm volatile("ldmatrix.sync.aligned.m8n8.x4.shared.b16 {%0,%1,%2,%3}, [%4];\n"
                 : "=r"(r0), "=r"(r1), "=r"(r2), "=r"(r3) : "r"(addr));
}
__device__ __forceinline__ void ldsm_x4_t(unsigned& r0, unsigned& r1, unsigned& r2, unsigned& r3,
                                          uint32_t addr) {
    asm volatile("ldmatrix.sync.aligned.m8n8.x4.trans.shared.b16 {%0,%1,%2,%3}, [%4];\n"
                 : "=r"(r0), "=r"(r1), "=r"(r2), "=r"(r3) : "r"(addr));
}

__device__ __forceinline__ void cp_async16(uint32_t smem_addr, const void* gptr) {
    asm volatile("cp.async.cg.shared.global [%0], [%1], 16;\n"
                 :: "r"(smem_addr), "l"(gptr));
}
__device__ __forceinline__ void cp_commit() { asm volatile("cp.async.commit_group;\n"); }
__device__ __forceinline__ void cp_wait1()  { asm volatile("cp.async.wait_group 1;\n"); }
__device__ __forceinline__ void cp_wait0()  { asm volatile("cp.async.wait_group 0;\n"); }

// ---------------------------------------------------------------------
// Smem geometry (halves): BK=64 per stage, 3 stages.
// ---------------------------------------------------------------------
#define ASTR 72
#define BSTR 136
#define NSTG 3
#define A_TILE_B (128 * ASTR * 2)          // 18432 B
#define B_TILE_B (64 * BSTR * 2)           // 17408 B
#define OFF_TOKS 0
#define OFF_A    512
#define OFF_B    (OFF_A + NSTG * A_TILE_B)           // 55808
#define SMEM_TOTAL (OFF_B + NSTG * B_TILE_B)         // 108032 (~105.5 KB)

// ---------------------------------------------------------------------
// fp16 grouped GEMM (mma.sync.m16n8k16), 128x128 CTA tile, BK=64/stage.
// NEW: per-warp ni (16-row granularity) skips MMA work on padding rows.
// ---------------------------------------------------------------------
template<int KD, int ND, bool G1>
__global__ void __launch_bounds__(256, 2)
k_gemm_f16(const __half* __restrict__ Ain,
           const __half* __restrict__ W,
           const float* __restrict__ bias,
           float* __restrict__ out,
           const int* __restrict__ kp,
           const float* __restrict__ cvt_src,
           __half* __restrict__ cvt_dst,
           int cvt_n8)
{
    constexpr int NK = KD / 64;
    const int ti = blockIdx.y;

    if (ti < g_ntiles) {
        const int e    = g_tile_e[ti];
        const int m0   = g_tile_m[ti];
        const int cnt  = g_counts[e];
        const int base = g_base[e];
        const int n0   = blockIdx.x * 128;

        extern __shared__ __align__(16) char smem[];
        int* toks = reinterpret_cast<int*>(smem + OFF_TOKS);

        const int tid  = threadIdx.x;
        const int lane = tid & 31;
        const int wid  = tid >> 5;
        const int wm   = wid >> 2;     // 0..1
        const int wn   = wid & 3;      // 0..3
        const int g    = lane >> 2;    // 0..7
        const int c    = lane & 3;     // 0..3

        if (tid < 128) {
            int row = m0 + tid;
            toks[tid] = (row < cnt) ? g_lists[e][row] : 0;
        }
        __syncthreads();

        // number of active 16-row i-steps for this warp (uniform, k-invariant)
        const int rem = cnt - m0 - wm * 64;
        const int ni  = (rem >= 64) ? 4 : ((rem <= 0) ? 0 : ((rem + 15) >> 4));

        const uint32_t sb  = (uint32_t)__cvta_generic_to_shared(smem);
        const uint32_t sbA = sb + OFF_A;
        const uint32_t sbB = sb + OFF_B;

        // ---- A staging: 4 chunks/thread ----
        const int aq = tid & 7;
        const __half* aSrc[4];
        uint32_t aDst[4];
#pragma unroll
        for (int i = 0; i < 4; i++) {
            int m = (tid >> 3) + 32 * i;
            int row = m0 + m;
            if (G1) aSrc[i] = Ain + (size_t)toks[m] * KD + 8 * aq;
            else    aSrc[i] = g_hh + (size_t)((row < cnt) ? base + row : base) * KD + 8 * aq;
            aDst[i] = (uint32_t)(m * (ASTR * 2) + aq * 16);
        }
        // ---- B staging: 4 chunks/thread ----
        const int bnq = tid & 15;
        const int bk0 = tid >> 4;
        const __half* Wp = W + (size_t)e * KD * ND;

        auto load_stage = [&](int kt, int buf) {
            const int k0 = kt * 64;
            const uint32_t dA = sbA + buf * A_TILE_B;
            const uint32_t dB = sbB + buf * B_TILE_B;
#pragma unroll
            for (int i = 0; i < 4; i++)
                cp_async16(dA + aDst[i], aSrc[i] + k0);
#pragma unroll
            for (int i = 0; i < 4; i++) {
                int k = bk0 + 16 * i;
                cp_async16(dB + (uint32_t)(k * (BSTR * 2) + bnq * 16),
                           Wp + (size_t)(k0 + k) * ND + n0 + 8 * bnq);
            }
            cp_commit();
        };

        float acc[4][4][4];
#pragma unroll
        for (int i = 0; i < 4; i++)
#pragma unroll
            for (int j = 0; j < 4; j++)
#pragma unroll
                for (int r = 0; r < 4; r++) acc[i][j][r] = 0.f;

        load_stage(0, 0);
        load_stage(1, 1);

        const int lrow  = wm * 64 + (lane & 15);
        const int lakb  = (lane >> 4) * 16;
        const int bkrow = (lane & 7) + ((lane >> 4) << 3);
        const int bnb0  = ((lane >> 3) & 1) * 16 + (wn * 32) * 2;

        for (int kt = 0; kt < NK; kt++) {
            const int buf = kt % NSTG;
            if (kt + 1 < NK) cp_wait1(); else cp_wait0();
            __syncthreads();
            if (kt + 2 < NK) load_stage(kt + 2, (kt + 2) % NSTG);

            const uint32_t Ab = sbA + buf * A_TILE_B;
            const uint32_t Bb = sbB + buf * B_TILE_B;

            if (ni == 4) {
                // full path (common case) — fully unrolled
#pragma unroll
                for (int h = 0; h < 4; h++) {
                    unsigned b0[4], b1[4];
#pragma unroll
                    for (int t = 0; t < 2; t++) {
                        unsigned r0, r1, r2, r3;
                        uint32_t baddr = Bb + (uint32_t)((h * 16 + bkrow) * (BSTR * 2)
                                                         + bnb0 + t * 32);
                        ldsm_x4_t(r0, r1, r2, r3, baddr);
                        b0[2 * t]     = r0;  b0[2 * t + 1] = r1;
                        b1[2 * t]     = r2;  b1[2 * t + 1] = r3;
                    }
#pragma unroll
                    for (int i = 0; i < 4; i++) {
                        unsigned a0, a1, a2, a3;
                        uint32_t aaddr = Ab + (uint32_t)((lrow + i * 16) * (ASTR * 2)
                                                         + h * 32 + lakb);
                        ldsm_x4(a0, a1, a2, a3, aaddr);
#pragma unroll
                        for (int j = 0; j < 4; j++)
                            mma_f16(acc[i][j][0], acc[i][j][1], acc[i][j][2], acc[i][j][3],
                                    a0, a1, a2, a3, b0[j], b1[j]);
                    }
                }
            } else if (ni != 0) {
                // partial path — dynamic i-bound (padding rows skipped)
#pragma unroll
                for (int h = 0; h < 4; h++) {
                    unsigned b0[4], b1[4];
#pragma unroll
                    for (int t = 0; t < 2; t++) {
                        unsigned r0, r1, r2, r3;
                        uint32_t baddr = Bb + (uint32_t)((h * 16 + bkrow) * (BSTR * 2)
                                                         + bnb0 + t * 32);
                        ldsm_x4_t(r0, r1, r2, r3, baddr);
                        b0[2 * t]     = r0;  b0[2 * t + 1] = r1;
                        b1[2 * t]     = r2;  b1[2 * t + 1] = r3;
                    }
                    for (int i = 0; i < ni; i++) {
                        unsigned a0, a1, a2, a3;
                        uint32_t aaddr = Ab + (uint32_t)((lrow + i * 16) * (ASTR * 2)
                                                         + h * 32 + lakb);
                        ldsm_x4(a0, a1, a2, a3, aaddr);
#pragma unroll
                        for (int j = 0; j < 4; j++)
                            mma_f16(acc[i][j][0], acc[i][j][1], acc[i][j][2], acc[i][j][3],
                                    a0, a1, a2, a3, b0[j], b1[j]);
                    }
                }
            }
            // ni == 0: no compute for this warp (padding band)
        }

        // ---- epilogue ----
        if (G1) {
#pragma unroll
            for (int j = 0; j < 4; j++) {
                int col = n0 + wn * 32 + j * 8 + 2 * c;
                float bv0 = __ldg(bias + (size_t)e * ND + col);
                float bv1 = __ldg(bias + (size_t)e * ND + col + 1);
#pragma unroll
                for (int i = 0; i < 4; i++) {
                    int r0 = m0 + wm * 64 + i * 16 + g;
                    if (r0 < cnt) {
                        __half2 v = __floats2half2_rn(fmaxf(acc[i][j][0] + bv0, 0.f),
                                                      fmaxf(acc[i][j][1] + bv1, 0.f));
                        *reinterpret_cast<__half2*>(&g_hh[(size_t)(base + r0) * ND + col]) = v;
                    }
                    int r1 = r0 + 8;
                    if (r1 < cnt) {
                        __half2 v = __floats2half2_rn(fmaxf(acc[i][j][2] + bv0, 0.f),
                                                      fmaxf(acc[i][j][3] + bv1, 0.f));
                        *reinterpret_cast<__half2*>(&g_hh[(size_t)(base + r1) * ND + col]) = v;
                    }
                }
            }
        } else {
            int kv = kp ? __ldg(kp) : Kq;
            if (kv <= 0) kv = Kq;
            float inv_k = 1.0f / (float)kv;
#pragma unroll
            for (int j = 0; j < 4; j++) {
                int col = n0 + wn * 32 + j * 8 + 2 * c;
                float bv0 = __ldg(bias + (size_t)e * ND + col);
                float bv1 = __ldg(bias + (size_t)e * ND + col + 1);
#pragma unroll
                for (int i = 0; i < 4; i++) {
                    int r0 = m0 + wm * 64 + i * 16 + g;
                    if (r0 < cnt) {
                        float* op = out + (size_t)toks[r0 - m0] * ND + col;
                        atomicAdd(op,     (acc[i][j][0] + bv0) * inv_k);
                        atomicAdd(op + 1, (acc[i][j][1] + bv1) * inv_k);
                    }
                    int r1 = r0 + 8;
                    if (r1 < cnt) {
                        float* op = out + (size_t)toks[r1 - m0] * ND + col;
                        atomicAdd(op,     (acc[i][j][2] + bv0) * inv_k);
                        atomicAdd(op + 1, (acc[i][j][3] + bv1) * inv_k);
                    }
                }
            }
        }
    }

    // ---- fused conversion tail (all CTAs, incl. early-return ones) ----
    if (cvt_src) {
        int gtid = (blockIdx.y * gridDim.x + blockIdx.x) * blockDim.x + threadIdx.x;
        int gstride = gridDim.x * gridDim.y * blockDim.x;
        for (int i = gtid; i < cvt_n8; i += gstride) {
            float4 a = reinterpret_cast<const float4*>(cvt_src)[2 * i];
            float4 b = reinterpret_cast<const float4*>(cvt_src)[2 * i + 1];
            __half2 h0 = __floats2half2_rn(a.x, a.y);
            __half2 h1 = __floats2half2_rn(a.z, a.w);
            __half2 h2 = __floats2half2_rn(b.x, b.y);
            __half2 h3 = __floats2half2_rn(b.z, b.w);
            uint4 o;
            o.x = reinterpret_cast<unsigned&>(h0);
            o.y = reinterpret_cast<unsigned&>(h1);
            o.z = reinterpret_cast<unsigned&>(h2);
            o.w = reinterpret_cast<unsigned&>(h3);
            reinterpret_cast<uint4*>(cvt_dst)[i] = o;
        }
    }
}

// ---------------------------------------------------------------------
// launch
// ---------------------------------------------------------------------
extern "C" void kernel_launch(void* const* d_in, const int* in_sizes, int n_in,
                              void* d_out, int out_size) {
    const float* x      = (const float*)d_in[0];
    const float* W1     = (const float*)d_in[1];
    const float* b1     = (const float*)d_in[2];
    const float* W2     = (const float*)d_in[3];
    const float* b2     = (const float*)d_in[4];
    const int*   assign = (const int*)d_in[5];
    const int*   kp     = (n_in >= 7) ? (const int*)d_in[6] : nullptr;
    float* out = (float*)d_out;

    __half *w2h, *xh, *w1h;
    cudaGetSymbolAddress((void**)&w2h, g_w2h);
    cudaGetSymbolAddress((void**)&xh,  g_xh);
    cudaGetSymbolAddress((void**)&w1h, g_w1h);

    // 1) all independent front-end work in one wide launch
    k_prep<<<4096, 256>>>(out, out_size / 4, x, W1, assign);

    // 2) router lists + tile table (last-block)
    k_build<<<16, 256>>>(assign);

    cudaFuncSetAttribute(k_gemm_f16<Dq, Hq, true>,
                         cudaFuncAttributeMaxDynamicSharedMemorySize, SMEM_TOTAL);
    cudaFuncSetAttribute(k_gemm_f16<Hq, Dq, false>,
                         cudaFuncAttributeMaxDynamicSharedMemorySize, SMEM_TOTAL);

    // 3) GEMM1 (+ fused W2 fp32->fp16 conversion)
    dim3 g1(Hq / 128, MAXTIL, 1);
    k_gemm_f16<Dq, Hq, true><<<g1, 256, SMEM_TOTAL>>>(
        xh, w1h, b1, nullptr, nullptr,
        W2, w2h, Eq * Hq * Dq / 8);

    // 4) GEMM2 -> scatter-add out
    dim3 g2(Dq / 128, MAXTIL, 1);
    k_gemm_f16<Hq, Dq, false><<<g2, 256, SMEM_TOTAL>>>(
        nullptr, w2h, b2, out, kp,
        nullptr, nullptr, 0);
}

// round 17
// speedup vs baseline: 2.2593x; 2.2593x over previous
#include <cuda_runtime.h>
#include <cuda_fp16.h>
#include <cstdint>

// Problem constants (fixed for MoELayer_20761871908984)
#define Bq     4
#define Sq     1024
#define Dq     1024
#define Hq     4096
#define Eq     8
#define Kq     2
#define NTOK   (Bq * Sq)        // 4096 tokens
#define MAXROW (NTOK * Kq)      // 8192 max (token, expert) rows
#define MAXTIL 72               // >= sum ceil(cnt_e/128) (bound 71)

// -------- device-global scratch (no runtime allocation allowed) --------
__device__ int    g_counts[Eq];
__device__ int    g_lists[Eq][NTOK];
__device__ int    g_odd_nonzero;             // sticky: 0 -> int64, 1 -> int32
__device__ int    g_done;                    // k_build completion counter
__device__ int    g_tile_e[MAXTIL];
__device__ int    g_tile_m[MAXTIL];
__device__ int    g_base[Eq];
__device__ int    g_ntiles;
__device__ __half g_xh [(size_t)NTOK * Dq];       //   8 MB x  (fp16 RNE)
__device__ __half g_hh [(size_t)MAXROW * Hq];     //  64 MB hidden (fp16 RNE)
__device__ __half g_w1h[(size_t)Eq * Dq * Hq];    //  64 MB W1 (fp16 RNE)
__device__ __half g_w2h[(size_t)Eq * Hq * Dq];    //  64 MB W2 (fp16 RNE)

// ---------------------------------------------------------------------
// k_prep: all independent front-end work in ONE launch.
// ---------------------------------------------------------------------
__global__ void k_prep(float* __restrict__ out, int n_out4,
                       const float* __restrict__ x,
                       const float* __restrict__ W1,
                       const int* __restrict__ a32) {
    const int i = blockIdx.x * blockDim.x + threadIdx.x;
    const int stride = gridDim.x * blockDim.x;

    if (i == 0) {
#pragma unroll
        for (int e = 0; e < Eq; e++) g_counts[e] = 0;
        g_done = 0;
    }

    // detect: odd 32-bit words nonzero <=> int32 layout
    if (i < NTOK * Kq / 2) {
        if (a32[2 * i + 1] != 0) atomicOr(&g_odd_nonzero, 1);
    }

    // zero output
    float4 z = make_float4(0.f, 0.f, 0.f, 0.f);
    for (int j = i; j < n_out4; j += stride)
        reinterpret_cast<float4*>(out)[j] = z;

    // x -> fp16 (8 elems/iter)
    const int nx8 = NTOK * Dq / 8;
    for (int j = i; j < nx8; j += stride) {
        float4 a = reinterpret_cast<const float4*>(x)[2 * j];
        float4 b = reinterpret_cast<const float4*>(x)[2 * j + 1];
        __half2 h0 = __floats2half2_rn(a.x, a.y);
        __half2 h1 = __floats2half2_rn(a.z, a.w);
        __half2 h2 = __floats2half2_rn(b.x, b.y);
        __half2 h3 = __floats2half2_rn(b.z, b.w);
        uint4 o;
        o.x = reinterpret_cast<unsigned&>(h0);
        o.y = reinterpret_cast<unsigned&>(h1);
        o.z = reinterpret_cast<unsigned&>(h2);
        o.w = reinterpret_cast<unsigned&>(h3);
        reinterpret_cast<uint4*>(g_xh)[j] = o;
    }

    // W1 -> fp16 (8 elems/iter)
    const int nw8 = Eq * Dq * Hq / 8;
    for (int j = i; j < nw8; j += stride) {
        float4 a = reinterpret_cast<const float4*>(W1)[2 * j];
        float4 b = reinterpret_cast<const float4*>(W1)[2 * j + 1];
        __half2 h0 = __floats2half2_rn(a.x, a.y);
        __half2 h1 = __floats2half2_rn(a.z, a.w);
        __half2 h2 = __floats2half2_rn(b.x, b.y);
        __half2 h3 = __floats2half2_rn(b.z, b.w);
        uint4 o;
        o.x = reinterpret_cast<unsigned&>(h0);
        o.y = reinterpret_cast<unsigned&>(h1);
        o.z = reinterpret_cast<unsigned&>(h2);
        o.w = reinterpret_cast<unsigned&>(h3);
        reinterpret_cast<uint4*>(g_w1h)[j] = o;
    }
}

// ---------------------------------------------------------------------
// k_build: per-expert token lists; LAST block also builds the tile table.
// ---------------------------------------------------------------------
__global__ void k_build(const int* __restrict__ a32) {
    int t = blockIdx.x * blockDim.x + threadIdx.x;
    if (t < NTOK) {
        int is64 = (g_odd_nonzero == 0);
        unsigned mask = 0;
#pragma unroll
        for (int j = 0; j < Kq; j++) {
            int e;
            if (is64) e = a32[(t * Kq + j) * 2];
            else      e = a32[t * Kq + j];
            mask |= 1u << (e & (Eq - 1));
        }
        while (mask) {
            int e = __ffs(mask) - 1;
            mask &= mask - 1;
            int p = atomicAdd(&g_counts[e], 1);
            g_lists[e][p] = t;
        }
    }
    __syncthreads();
    if (threadIdx.x == 0) {
        __threadfence();
        int done = atomicAdd(&g_done, 1);
        if (done == (int)gridDim.x - 1) {
            int base = 0, nt = 0;
#pragma unroll
            for (int e = 0; e < Eq; e++) {
                int cnt = g_counts[e];
                g_base[e] = base;
                for (int m0 = 0; m0 < cnt && nt < MAXTIL; m0 += 128) {
                    g_tile_e[nt] = e;
                    g_tile_m[nt] = m0;
                    nt++;
                }
                base += cnt;
            }
            g_ntiles = nt;
        }
    }
}

// ---------------------------------------------------------------------
// fp16 MMA + ldmatrix + cp.async helpers
// ---------------------------------------------------------------------
__device__ __forceinline__ void mma_f16(float& d0, float& d1, float& d2, float& d3,
                                        unsigned a0, unsigned a1, unsigned a2, unsigned a3,
                                        unsigned b0, unsigned b1) {
    asm volatile(
        "mma.sync.aligned.m16n8k16.row.col.f32.f16.f16.f32 "
        "{%0,%1,%2,%3},{%4,%5,%6,%7},{%8,%9},{%0,%1,%2,%3};\n"
        : "+f"(d0), "+f"(d1), "+f"(d2), "+f"(d3)
        : "r"(a0), "r"(a1), "r"(a2), "r"(a3), "r"(b0), "r"(b1));
}

__device__ __forceinline__ void ldsm_x4(unsigned& r0, unsigned& r1, unsigned& r2, unsigned& r3,
                                        uint32_t addr) {
    asm volatile("ldmatrix.sync.aligned.m8n8.x4.shared.b16 {%0,%1,%2,%3}, [%4];\n"
                 : "=r"(r0), "=r"(r1), "=r"(r2), "=r"(r3) : "r"(addr));
}
__device__ __forceinline__ void ldsm_x4_t(unsigned& r0, unsigned& r1, unsigned& r2, unsigned& r3,
                                          uint32_t addr) {
    asm volatile("ldmatrix.sync.aligned.m8n8.x4.trans.shared.b16 {%0,%1,%2,%3}, [%4];\n"
                 : "=r"(r0), "=r"(r1), "=r"(r2), "=r"(r3) : "r"(addr));
}

__device__ __forceinline__ void cp_async16(uint32_t smem_addr, const void* gptr) {
    asm volatile("cp.async.cg.shared.global [%0], [%1], 16;\n"
                 :: "r"(smem_addr), "l"(gptr));
}
__device__ __forceinline__ void cp_commit() { asm volatile("cp.async.commit_group;\n"); }
__device__ __forceinline__ void cp_wait1()  { asm volatile("cp.async.wait_group 1;\n"); }
__device__ __forceinline__ void cp_wait0()  { asm volatile("cp.async.wait_group 0;\n"); }

// ---------------------------------------------------------------------
// Smem geometry (halves): BK=64 per stage, 3 stages.
// ---------------------------------------------------------------------
#define ASTR 72
#define BSTR 136
#define NSTG 3
#define A_TILE_B (128 * ASTR * 2)          // 18432 B
#define B_TILE_B (64 * BSTR * 2)           // 17408 B
#define OFF_TOKS 0
#define OFF_A    512
#define OFF_B    (OFF_A + NSTG * A_TILE_B)           // 55808
#define SMEM_TOTAL (OFF_B + NSTG * B_TILE_B)         // 108032 (~105.5 KB)

// ---------------------------------------------------------------------
// fp16 grouped GEMM (mma.sync.m16n8k16), 128x128 CTA tile, BK=64/stage.
// Band-level padding skip: warp-uniform branch, both sides fully unrolled
// (R16 lesson: no runtime-bounded loops around MMA register accumulation).
// ---------------------------------------------------------------------
template<int KD, int ND, bool G1>
__global__ void __launch_bounds__(256, 2)
k_gemm_f16(const __half* __restrict__ Ain,
           const __half* __restrict__ W,
           const float* __restrict__ bias,
           float* __restrict__ out,
           const int* __restrict__ kp,
           const float* __restrict__ cvt_src,
           __half* __restrict__ cvt_dst,
           int cvt_n8)
{
    constexpr int NK = KD / 64;
    const int ti = blockIdx.y;

    if (ti < g_ntiles) {
        const int e    = g_tile_e[ti];
        const int m0   = g_tile_m[ti];
        const int cnt  = g_counts[e];
        const int base = g_base[e];
        const int n0   = blockIdx.x * 128;

        extern __shared__ __align__(16) char smem[];
        int* toks = reinterpret_cast<int*>(smem + OFF_TOKS);

        const int tid  = threadIdx.x;
        const int lane = tid & 31;
        const int wid  = tid >> 5;
        const int wm   = wid >> 2;     // 0..1
        const int wn   = wid & 3;      // 0..3
        const int g    = lane >> 2;    // 0..7
        const int c    = lane & 3;     // 0..3

        if (tid < 128) {
            int row = m0 + tid;
            toks[tid] = (row < cnt) ? g_lists[e][row] : 0;
        }
        __syncthreads();

        // warp-uniform: does this 64-row band contain any live rows?
        const bool band_live = (cnt - m0 - wm * 64) > 0;

        const uint32_t sb  = (uint32_t)__cvta_generic_to_shared(smem);
        const uint32_t sbA = sb + OFF_A;
        const uint32_t sbB = sb + OFF_B;

        // ---- A staging: 4 chunks/thread ----
        const int aq = tid & 7;
        const __half* aSrc[4];
        uint32_t aDst[4];
#pragma unroll
        for (int i = 0; i < 4; i++) {
            int m = (tid >> 3) + 32 * i;
            int row = m0 + m;
            if (G1) aSrc[i] = Ain + (size_t)toks[m] * KD + 8 * aq;
            else    aSrc[i] = g_hh + (size_t)((row < cnt) ? base + row : base) * KD + 8 * aq;
            aDst[i] = (uint32_t)(m * (ASTR * 2) + aq * 16);
        }
        // ---- B staging: 4 chunks/thread ----
        const int bnq = tid & 15;
        const int bk0 = tid >> 4;
        const __half* Wp = W + (size_t)e * KD * ND;

        auto load_stage = [&](int kt, int buf) {
            const int k0 = kt * 64;
            const uint32_t dA = sbA + buf * A_TILE_B;
            const uint32_t dB = sbB + buf * B_TILE_B;
#pragma unroll
            for (int i = 0; i < 4; i++)
                cp_async16(dA + aDst[i], aSrc[i] + k0);
#pragma unroll
            for (int i = 0; i < 4; i++) {
                int k = bk0 + 16 * i;
                cp_async16(dB + (uint32_t)(k * (BSTR * 2) + bnq * 16),
                           Wp + (size_t)(k0 + k) * ND + n0 + 8 * bnq);
            }
            cp_commit();
        };

        float acc[4][4][4];
#pragma unroll
        for (int i = 0; i < 4; i++)
#pragma unroll
            for (int j = 0; j < 4; j++)
#pragma unroll
                for (int r = 0; r < 4; r++) acc[i][j][r] = 0.f;

        load_stage(0, 0);
        load_stage(1, 1);

        const int lrow  = wm * 64 + (lane & 15);
        const int lakb  = (lane >> 4) * 16;
        const int bkrow = (lane & 7) + ((lane >> 4) << 3);
        const int bnb0  = ((lane >> 3) & 1) * 16 + (wn * 32) * 2;

        for (int kt = 0; kt < NK; kt++) {
            const int buf = kt % NSTG;
            if (kt + 1 < NK) cp_wait1(); else cp_wait0();
            __syncthreads();
            if (kt + 2 < NK) load_stage(kt + 2, (kt + 2) % NSTG);

            if (band_live) {
                const uint32_t Ab = sbA + buf * A_TILE_B;
                const uint32_t Bb = sbB + buf * B_TILE_B;
#pragma unroll
                for (int h = 0; h < 4; h++) {
                    unsigned b0[4], b1[4];
#pragma unroll
                    for (int t = 0; t < 2; t++) {
                        unsigned r0, r1, r2, r3;
                        uint32_t baddr = Bb + (uint32_t)((h * 16 + bkrow) * (BSTR * 2)
                                                         + bnb0 + t * 32);
                        ldsm_x4_t(r0, r1, r2, r3, baddr);
                        b0[2 * t]     = r0;  b0[2 * t + 1] = r1;
                        b1[2 * t]     = r2;  b1[2 * t + 1] = r3;
                    }
#pragma unroll
                    for (int i = 0; i < 4; i++) {
                        unsigned a0, a1, a2, a3;
                        uint32_t aaddr = Ab + (uint32_t)((lrow + i * 16) * (ASTR * 2)
                                                         + h * 32 + lakb);
                        ldsm_x4(a0, a1, a2, a3, aaddr);
#pragma unroll
                        for (int j = 0; j < 4; j++)
                            mma_f16(acc[i][j][0], acc[i][j][1], acc[i][j][2], acc[i][j][3],
                                    a0, a1, a2, a3, b0[j], b1[j]);
                    }
                }
            }
        }

        // ---- epilogue ----
        if (G1) {
#pragma unroll
            for (int j = 0; j < 4; j++) {
                int col = n0 + wn * 32 + j * 8 + 2 * c;
                float bv0 = __ldg(bias + (size_t)e * ND + col);
                float bv1 = __ldg(bias + (size_t)e * ND + col + 1);
#pragma unroll
                for (int i = 0; i < 4; i++) {
                    int r0 = m0 + wm * 64 + i * 16 + g;
                    if (r0 < cnt) {
                        __half2 v = __floats2half2_rn(fmaxf(acc[i][j][0] + bv0, 0.f),
                                                      fmaxf(acc[i][j][1] + bv1, 0.f));
                        *reinterpret_cast<__half2*>(&g_hh[(size_t)(base + r0) * ND + col]) = v;
                    }
                    int r1 = r0 + 8;
                    if (r1 < cnt) {
                        __half2 v = __floats2half2_rn(fmaxf(acc[i][j][2] + bv0, 0.f),
                                                      fmaxf(acc[i][j][3] + bv1, 0.f));
                        *reinterpret_cast<__half2*>(&g_hh[(size_t)(base + r1) * ND + col]) = v;
                    }
                }
            }
        } else {
            int kv = kp ? __ldg(kp) : Kq;
            if (kv <= 0) kv = Kq;
            float inv_k = 1.0f / (float)kv;
#pragma unroll
            for (int j = 0; j < 4; j++) {
                int col = n0 + wn * 32 + j * 8 + 2 * c;
                float bv0 = __ldg(bias + (size_t)e * ND + col);
                float bv1 = __ldg(bias + (size_t)e * ND + col + 1);
#pragma unroll
                for (int i = 0; i < 4; i++) {
                    int r0 = m0 + wm * 64 + i * 16 + g;
                    if (r0 < cnt) {
                        float* op = out + (size_t)toks[r0 - m0] * ND + col;
                        atomicAdd(op,     (acc[i][j][0] + bv0) * inv_k);
                        atomicAdd(op + 1, (acc[i][j][1] + bv1) * inv_k);
                    }
                    int r1 = r0 + 8;
                    if (r1 < cnt) {
                        float* op = out + (size_t)toks[r1 - m0] * ND + col;
                        atomicAdd(op,     (acc[i][j][2] + bv0) * inv_k);
                        atomicAdd(op + 1, (acc[i][j][3] + bv1) * inv_k);
                    }
                }
            }
        }
    }

    // ---- fused conversion tail (all CTAs, incl. early-return ones) ----
    if (cvt_src) {
        int gtid = (blockIdx.y * gridDim.x + blockIdx.x) * blockDim.x + threadIdx.x;
        int gstride = gridDim.x * gridDim.y * blockDim.x;
        for (int i = gtid; i < cvt_n8; i += gstride) {
            float4 a = reinterpret_cast<const float4*>(cvt_src)[2 * i];
            float4 b = reinterpret_cast<const float4*>(cvt_src)[2 * i + 1];
            __half2 h0 = __floats2half2_rn(a.x, a.y);
            __half2 h1 = __floats2half2_rn(a.z, a.w);
            __half2 h2 = __floats2half2_rn(b.x, b.y);
            __half2 h3 = __floats2half2_rn(b.z, b.w);
            uint4 o;
            o.x = reinterpret_cast<unsigned&>(h0);
            o.y = reinterpret_cast<unsigned&>(h1);
            o.z = reinterpret_cast<unsigned&>(h2);
            o.w = reinterpret_cast<unsigned&>(h3);
            reinterpret_cast<uint4*>(cvt_dst)[i] = o;
        }
    }
}

// ---------------------------------------------------------------------
// launch
// ---------------------------------------------------------------------
extern "C" void kernel_launch(void* const* d_in, const int* in_sizes, int n_in,
                              void* d_out, int out_size) {
    const float* x      = (const float*)d_in[0];
    const float* W1     = (const float*)d_in[1];
    const float* b1     = (const float*)d_in[2];
    const float* W2     = (const float*)d_in[3];
    const float* b2     = (const float*)d_in[4];
    const int*   assign = (const int*)d_in[5];
    const int*   kp     = (n_in >= 7) ? (const int*)d_in[6] : nullptr;
    float* out = (float*)d_out;

    __half *w2h, *xh, *w1h;
    cudaGetSymbolAddress((void**)&w2h, g_w2h);
    cudaGetSymbolAddress((void**)&xh,  g_xh);
    cudaGetSymbolAddress((void**)&w1h, g_w1h);

    // 1) all independent front-end work in one wide launch
    k_prep<<<4096, 256>>>(out, out_size / 4, x, W1, assign);

    // 2) router lists + tile table (last-block)
    k_build<<<16, 256>>>(assign);

    cudaFuncSetAttribute(k_gemm_f16<Dq, Hq, true>,
                         cudaFuncAttributeMaxDynamicSharedMemorySize, SMEM_TOTAL);
    cudaFuncSetAttribute(k_gemm_f16<Hq, Dq, false>,
                         cudaFuncAttributeMaxDynamicSharedMemorySize, SMEM_TOTAL);

    // 3) GEMM1 (+ fused W2 fp32->fp16 conversion)
    dim3 g1(Hq / 128, MAXTIL, 1);
    k_gemm_f16<Dq, Hq, true><<<g1, 256, SMEM_TOTAL>>>(
        xh, w1h, b1, nullptr, nullptr,
        W2, w2h, Eq * Hq * Dq / 8);

    // 4) GEMM2 -> scatter-add out
    dim3 g2(Dq / 128, MAXTIL, 1);
    k_gemm_f16<Hq, Dq, false><<<g2, 256, SMEM_TOTAL>>>(
        nullptr, w2h, b2, out, kp,
        nullptr, nullptr, 0);
}